// round 15
// baseline (speedup 1.0000x reference)
#include <cuda_runtime.h>
#include <cuda_bf16.h>
#include <math.h>

// ---------------- problem constants ----------------
#define VSZ   32000
#define ESZ   512
#define HSZ   1024
#define TXN   2048
#define TYN   512
#define G4    4096
#define MARGIN 0.03f

// ---------------- device scratch ----------------
// G layout: [blk(128)][t(2048)][gate(4)][ui(8)]
__device__ float g_G[(size_t)TXN * G4];
__device__ float g_seq[(size_t)TXN * HSZ];
__device__ unsigned g_owbf[(size_t)VSZ * HSZ / 2];   // bf16 out_w (65.5MB)
__device__ float g_h[2][HSZ];
__device__ float g_hlast[HSZ];
__device__ float g_f1[HSZ];
__device__ float g_hinit[HSZ];
__device__ float g_aw0[2][G4];
__device__ float g_d1f[HSZ];
__device__ unsigned long long g_amax[TYN - 1];
__device__ unsigned int g_bars[4];

// ---------------- helpers ----------------
__device__ __forceinline__ float wredsum(float v) {
#pragma unroll
    for (int o = 16; o; o >>= 1) v += __shfl_xor_sync(0xffffffffu, v, o);
    return v;
}
__device__ __forceinline__ double wredsum_d(double v) {
#pragma unroll
    for (int o = 16; o; o >>= 1) v += __shfl_xor_sync(0xffffffffu, v, o);
    return v;
}
__device__ __forceinline__ float bflo(unsigned u) { return __uint_as_float(u << 16); }
__device__ __forceinline__ float bfhi(unsigned u) { return __uint_as_float(u & 0xFFFF0000u); }

__device__ __forceinline__ unsigned long long mkkey(float v, int idx) {
    unsigned u = __float_as_uint(v);
    u = (u & 0x80000000u) ? ~u : (u | 0x80000000u);
    return ((unsigned long long)u << 32) |
           (unsigned long long)(0xFFFFFFFFu - (unsigned)idx);
}

__device__ __forceinline__ void gates4_f(float a0, float a1, float a2, float a3,
                                         float addv, int lane,
                                         float& i_, float& f_, float& g_, float& o_) {
    float asel = (lane == 0) ? a0 : (lane == 1) ? a1 : (lane == 2) ? a2 : a3;
    float gv = 0.0f;
    if (lane < 4) {
        float x = asel + addv;
        gv = (lane == 2) ? tanhf(x) : 1.0f / (1.0f + expf(-x));
    }
    i_ = __shfl_sync(0xffffffffu, gv, 0);
    f_ = __shfl_sync(0xffffffffu, gv, 1);
    g_ = __shfl_sync(0xffffffffu, gv, 2);
    o_ = __shfl_sync(0xffffffffu, gv, 3);
}

// release/acquire software grid barrier (single counter)
__device__ __forceinline__ void gbar(unsigned int* cnt, unsigned int& epoch) {
    epoch += gridDim.x;
    __syncthreads();
    if (threadIdx.x == 0) {
        asm volatile("red.release.gpu.global.add.u32 [%0], %1;"
                     :: "l"(cnt), "r"(1u) : "memory");
        unsigned cur;
        do {
            asm volatile("ld.acquire.gpu.global.u32 %0, [%1];"
                         : "=r"(cur) : "l"(cnt) : "memory");
        } while ((int)(cur - epoch) < 0);
    }
    __syncthreads();
}

// ---------------- init ----------------
__global__ void init_kernel() {
    int i = threadIdx.x;
    if (i < 4) g_bars[i] = 0u;
    for (int j = i; j < TYN - 1; j += blockDim.x) g_amax[j] = 0ull;
}

// ---------------- out_w fp32 -> bf16 (one-time) ----------------
__global__ void conv_bf16(const float* __restrict__ w) {
    size_t i = (size_t)blockIdx.x * blockDim.x + threadIdx.x;
    float4 v = *(const float4*)(w + i * 4);
    unsigned b0 = (unsigned)__bfloat16_as_ushort(__float2bfloat16_rn(v.x)) |
                  ((unsigned)__bfloat16_as_ushort(__float2bfloat16_rn(v.y)) << 16);
    unsigned b1 = (unsigned)__bfloat16_as_ushort(__float2bfloat16_rn(v.z)) |
                  ((unsigned)__bfloat16_as_ushort(__float2bfloat16_rn(v.w)) << 16);
    g_owbf[i * 2] = b0;
    g_owbf[i * 2 + 1] = b1;
}

// ---------------- tiled GEMM (fp32) with block-major transposed output ----------------
template <int KDIM>
__global__ void gemm_nt(const float* __restrict__ A, const int* __restrict__ ridx,
                        const float* __restrict__ B, const float* __restrict__ bias,
                        float* __restrict__ C) {
    __shared__ float As[64][17];
    __shared__ float Bs[64][17];
    int tid = threadIdx.x;
    int m0 = blockIdx.y * 64, n0 = blockIdx.x * 64;
    int tx = tid & 15, ty = tid >> 4;
    int lrow = tid >> 2;
    int lk4 = (tid & 3) * 4;
    const float* arow = A + (size_t)(ridx ? ridx[m0 + lrow] : (m0 + lrow)) * KDIM;
    const float* brow = B + (size_t)(n0 + lrow) * KDIM;
    float acc[4][4] = {};
    for (int kb = 0; kb < KDIM; kb += 16) {
        float4 av = *(const float4*)(arow + kb + lk4);
        float4 bv = *(const float4*)(brow + kb + lk4);
        __syncthreads();
        As[lrow][lk4 + 0] = av.x; As[lrow][lk4 + 1] = av.y;
        As[lrow][lk4 + 2] = av.z; As[lrow][lk4 + 3] = av.w;
        Bs[lrow][lk4 + 0] = bv.x; Bs[lrow][lk4 + 1] = bv.y;
        Bs[lrow][lk4 + 2] = bv.z; Bs[lrow][lk4 + 3] = bv.w;
        __syncthreads();
#pragma unroll
        for (int kk = 0; kk < 16; kk++) {
            float a[4], b[4];
#pragma unroll
            for (int i = 0; i < 4; i++) a[i] = As[ty * 4 + i][kk];
#pragma unroll
            for (int j = 0; j < 4; j++) b[j] = Bs[tx * 4 + j][kk];
#pragma unroll
            for (int i = 0; i < 4; i++)
#pragma unroll
                for (int j = 0; j < 4; j++) acc[i][j] += a[i] * b[j];
        }
    }
    int nb = n0 + tx * 4;
    int gate = nb >> 10;
    int u = nb & 1023;
    int blk = u >> 3, ui = u & 7;
    float4 b4 = __ldg((const float4*)(bias + nb));
    float* cb = C + (size_t)blk * (TXN * 32) + gate * 8 + ui;
#pragma unroll
    for (int i = 0; i < 4; i++) {
        int m = m0 + ty * 4 + i;
        float4 v = make_float4(acc[i][0] + b4.x, acc[i][1] + b4.y,
                               acc[i][2] + b4.z, acc[i][3] + b4.w);
        *(float4*)(cb + (size_t)m * 32) = v;
    }
}

// ---------------- persistent encoder LSTM scan — register-resident Whh (R12) ----------------
template <int WRITE_SEQ, int WRITE_LAST, int BARIDX>
__global__ void __launch_bounds__(512, 1)
enc_scan(const float* __restrict__ Whh, const float* __restrict__ G,
         float* __restrict__ seq) {
    __shared__ float sh[HSZ];
    __shared__ float spart[8][4];
    int tid = threadIdx.x, w = tid >> 5, lane = tid & 31;
    int ui = w >> 1, half = w & 1;
    int unit = blockIdx.x * 8 + ui;
    float4 wr[4][4];
#pragma unroll
    for (int g = 0; g < 4; g++) {
        const float* bg = Whh + (size_t)(g * 1024 + unit) * 1024 + half * 512;
#pragma unroll
        for (int j = 0; j < 4; j++)
            wr[g][j] = __ldg((const float4*)(bg + j * 128 + lane * 4));
    }
    if (blockIdx.x == 0)
        for (int i = tid; i < HSZ; i += blockDim.x) g_h[0][i] = 0.0f;
    unsigned int epoch = 0;
    unsigned int* bar = &g_bars[BARIDX];
    const float* gp = G + (size_t)blockIdx.x * (TXN * 32);
    gbar(bar, epoch);
    float c = 0.0f;
    int cur = 0;
    for (int t = 0; t < TXN; t++) {
        float addv = 0.0f;
        if (half == 0 && lane < 4) addv = __ldg(gp + t * 32 + lane * 8 + ui);
        if (tid == 256 && t + 16 < TXN)
            asm volatile("prefetch.global.L2 [%0];" :: "l"(gp + (t + 16) * 32));
        if (tid < 256)
            *(float4*)(sh + tid * 4) = __ldcg((const float4*)(&g_h[cur][tid * 4]));
        __syncthreads();
        float4 h4[4];
#pragma unroll
        for (int j = 0; j < 4; j++)
            h4[j] = *(float4*)(sh + half * 512 + j * 128 + lane * 4);
        float a0 = 0, a1 = 0, a2 = 0, a3 = 0;
#pragma unroll
        for (int j = 0; j < 4; j++) {
            a0 += wr[0][j].x * h4[j].x + wr[0][j].y * h4[j].y +
                  wr[0][j].z * h4[j].z + wr[0][j].w * h4[j].w;
            a1 += wr[1][j].x * h4[j].x + wr[1][j].y * h4[j].y +
                  wr[1][j].z * h4[j].z + wr[1][j].w * h4[j].w;
            a2 += wr[2][j].x * h4[j].x + wr[2][j].y * h4[j].y +
                  wr[2][j].z * h4[j].z + wr[2][j].w * h4[j].w;
            a3 += wr[3][j].x * h4[j].x + wr[3][j].y * h4[j].y +
                  wr[3][j].z * h4[j].z + wr[3][j].w * h4[j].w;
        }
        a0 = wredsum(a0); a1 = wredsum(a1); a2 = wredsum(a2); a3 = wredsum(a3);
        float asel = (lane == 0) ? a0 : (lane == 1) ? a1 : (lane == 2) ? a2 : a3;
        if (half == 1 && lane < 4) spart[ui][lane] = asel;
        __syncthreads();
        if (half == 0) {
            float gv = 0.0f;
            if (lane < 4) {
                float x = asel + spart[ui][lane] + addv;
                gv = (lane == 2) ? tanhf(x) : 1.0f / (1.0f + expf(-x));
            }
            float i_ = __shfl_sync(0xffffffffu, gv, 0);
            float f_ = __shfl_sync(0xffffffffu, gv, 1);
            float gg = __shfl_sync(0xffffffffu, gv, 2);
            float o_ = __shfl_sync(0xffffffffu, gv, 3);
            if (lane == 0) {
                c = f_ * c + i_ * gg;
                float h = o_ * tanhf(c);
                g_h[cur ^ 1][unit] = h;
                if (WRITE_SEQ) seq[(size_t)t * HSZ + unit] = h;
                if (WRITE_LAST && t == TXN - 1) g_hlast[unit] = h;
            }
        }
        gbar(bar, epoch);
        cur ^= 1;
    }
}

// ---------------- fc + relu (fp64, off hot path) ----------------
__global__ void fc_relu(const float* __restrict__ W, const float* __restrict__ b,
                        const float* __restrict__ in, float* __restrict__ out) {
    __shared__ double red[8];
    int r = blockIdx.x, tid = threadIdx.x, wid = tid >> 5, lane = tid & 31;
    const float* wr = W + (size_t)r * 1024;
    float4 w = __ldg((const float4*)(wr + tid * 4));
    float4 v = __ldg((const float4*)(in + tid * 4));
    double acc = (double)(w.x * v.x) + (double)(w.y * v.y) +
                 (double)(w.z * v.z) + (double)(w.w * v.w);
    acc = wredsum_d(acc);
    if (lane == 0) red[wid] = acc;
    __syncthreads();
    if (tid == 0) {
        double s = 0;
#pragma unroll
        for (int i = 0; i < 8; i++) s += red[i];
        double val = s + (double)__ldg(b + r);
        out[r] = (float)(val > 0.0 ? val : 0.0);
    }
}

// ---------------- persistent greedy decoder ----------------
#define DECT 512
__global__ void __launch_bounds__(DECT, 1)
decoder_kernel(
    const float* __restrict__ dWih0, const float* __restrict__ dWhh0, const float* __restrict__ db0,
    const float* __restrict__ dWih1, const float* __restrict__ dWhh1, const float* __restrict__ db1,
    const float* __restrict__ outw, const float* __restrict__ outb,
    const int* __restrict__ y, float* __restrict__ out) {
    __shared__ float sh0[HSZ];
    __shared__ float sh1[HSZ];
    __shared__ float c0s[HSZ];
    __shared__ float wih0s[G4];
    __shared__ float b0s[G4];
    __shared__ float slg[16][16];                 // per-warp phase-A logit stash
    __shared__ unsigned long long skeys[16];
    int tid = threadIdx.x, wid = tid >> 5, lane = tid & 31;
    int unit = wid * gridDim.x + blockIdx.x;
    unsigned int epoch = 0;
    unsigned int* bar = &g_bars[2];

    for (int i = tid; i < G4; i += DECT) {
        wih0s[i] = __ldg(dWih0 + i);
        b0s[i] = __ldg(db0 + i);
    }
    for (int i = tid; i < HSZ; i += DECT) {
        float v = __ldg(&g_hinit[i]);
        c0s[i] = v;
        sh0[i] = v;
    }
    __syncthreads();

    float c1 = 0.0f;
    if (unit < HSZ) c1 = __ldg(&g_hinit[unit]);

    float ah1p0 = 0, ah1p1 = 0, ah1p2 = 0, ah1p3 = 0;
    if (unit < HSZ) {
        float w0 = 0, w1 = 0, w2 = 0, w3 = 0;
        const float* bh0 = dWhh0 + (size_t)unit * 1024;
        const float* bh1 = dWhh1 + (size_t)unit * 1024;
#pragma unroll
        for (int k = 0; k < 8; k++) {
            int j = (k * 32 + lane) << 2;
            float4 h4 = *(float4*)(sh0 + j);
            float4 w;
            w = __ldg((const float4*)(bh0 + j));
            w0 += w.x * h4.x + w.y * h4.y + w.z * h4.z + w.w * h4.w;
            w = __ldg((const float4*)(bh0 + (1 << 20) + j));
            w1 += w.x * h4.x + w.y * h4.y + w.z * h4.z + w.w * h4.w;
            w = __ldg((const float4*)(bh0 + (2 << 20) + j));
            w2 += w.x * h4.x + w.y * h4.y + w.z * h4.z + w.w * h4.w;
            w = __ldg((const float4*)(bh0 + (3 << 20) + j));
            w3 += w.x * h4.x + w.y * h4.y + w.z * h4.z + w.w * h4.w;
            w = __ldg((const float4*)(bh1 + j));
            ah1p0 += w.x * h4.x + w.y * h4.y + w.z * h4.z + w.w * h4.w;
            w = __ldg((const float4*)(bh1 + (1 << 20) + j));
            ah1p1 += w.x * h4.x + w.y * h4.y + w.z * h4.z + w.w * h4.w;
            w = __ldg((const float4*)(bh1 + (2 << 20) + j));
            ah1p2 += w.x * h4.x + w.y * h4.y + w.z * h4.z + w.w * h4.w;
            w = __ldg((const float4*)(bh1 + (3 << 20) + j));
            ah1p3 += w.x * h4.x + w.y * h4.y + w.z * h4.z + w.w * h4.w;
        }
        w0 = wredsum(w0); w1 = wredsum(w1); w2 = wredsum(w2); w3 = wredsum(w3);
        ah1p0 = wredsum(ah1p0); ah1p1 = wredsum(ah1p1);
        ah1p2 = wredsum(ah1p2); ah1p3 = wredsum(ah1p3);
        float wsel = (lane == 0) ? w0 : (lane == 1) ? w1 : (lane == 2) ? w2 : w3;
        if (lane < 4) g_aw0[0][lane * 1024 + unit] = wsel;
    }
    gbar(bar, epoch);

    float xt0 = (float)__ldg(&y[0]);
    int gw = blockIdx.x * 16 + wid, nw = gridDim.x * 16;

    for (int t = 0; t < TYN - 1; t++) {
        float xt;
        if (t == 0) xt = xt0;
        else {
            unsigned long long key = __ldcg(&g_amax[t - 1]);
            xt = (float)(0xFFFFFFFFu - (unsigned int)(key & 0xFFFFFFFFull));
        }
        // ---- phase A: replicated layer0 ----
        {
            const float* aw = &g_aw0[t & 1][0];
#pragma unroll
            for (int uu = 0; uu < 2; uu++) {
                int u = tid + uu * DECT;
                float x0 = __ldcg(aw + u)        + (wih0s[u] * xt        + b0s[u]);
                float x1 = __ldcg(aw + 1024 + u) + (wih0s[1024 + u] * xt + b0s[1024 + u]);
                float x2 = __ldcg(aw + 2048 + u) + (wih0s[2048 + u] * xt + b0s[2048 + u]);
                float x3 = __ldcg(aw + 3072 + u) + (wih0s[3072 + u] * xt + b0s[3072 + u]);
                float i_ = 1.0f / (1.0f + expf(-x0));
                float f_ = 1.0f / (1.0f + expf(-x1));
                float gg = tanhf(x2);
                float o_ = 1.0f / (1.0f + expf(-x3));
                float c = f_ * c0s[u] + i_ * gg;
                c0s[u] = c;
                sh0[u] = o_ * tanhf(c);
            }
        }
        __syncthreads();
        // ---- phase B ----
        if (unit < HSZ) {
            float ai0 = 0, ai1 = 0, ai2 = 0, ai3 = 0;
            float w0 = 0, w1 = 0, w2 = 0, w3 = 0;
            const float* bi = dWih1 + (size_t)unit * 1024;
            const float* bh0 = dWhh0 + (size_t)unit * 1024;
#pragma unroll
            for (int k = 0; k < 8; k++) {
                int j = (k * 32 + lane) << 2;
                float4 h4 = *(float4*)(sh0 + j);
                float4 w;
                w = __ldg((const float4*)(bi + j));
                ai0 += w.x * h4.x + w.y * h4.y + w.z * h4.z + w.w * h4.w;
                w = __ldg((const float4*)(bi + (1 << 20) + j));
                ai1 += w.x * h4.x + w.y * h4.y + w.z * h4.z + w.w * h4.w;
                w = __ldg((const float4*)(bi + (2 << 20) + j));
                ai2 += w.x * h4.x + w.y * h4.y + w.z * h4.z + w.w * h4.w;
                w = __ldg((const float4*)(bi + (3 << 20) + j));
                ai3 += w.x * h4.x + w.y * h4.y + w.z * h4.z + w.w * h4.w;
                w = __ldg((const float4*)(bh0 + j));
                w0 += w.x * h4.x + w.y * h4.y + w.z * h4.z + w.w * h4.w;
                w = __ldg((const float4*)(bh0 + (1 << 20) + j));
                w1 += w.x * h4.x + w.y * h4.y + w.z * h4.z + w.w * h4.w;
                w = __ldg((const float4*)(bh0 + (2 << 20) + j));
                w2 += w.x * h4.x + w.y * h4.y + w.z * h4.z + w.w * h4.w;
                w = __ldg((const float4*)(bh0 + (3 << 20) + j));
                w3 += w.x * h4.x + w.y * h4.y + w.z * h4.z + w.w * h4.w;
            }
            ai0 = wredsum(ai0); ai1 = wredsum(ai1); ai2 = wredsum(ai2); ai3 = wredsum(ai3);
            w0 = wredsum(w0); w1 = wredsum(w1); w2 = wredsum(w2); w3 = wredsum(w3);
            float wsel = (lane == 0) ? w0 : (lane == 1) ? w1 : (lane == 2) ? w2 : w3;
            if (lane < 4) g_aw0[(t + 1) & 1][lane * 1024 + unit] = wsel;
            float addv = 0.0f;
            if (lane < 4) {
                float ap = (lane == 0) ? ah1p0 : (lane == 1) ? ah1p1
                         : (lane == 2) ? ah1p2 : ah1p3;
                addv = ap + __ldg(db1 + unit + lane * 1024);
            }
            float i_, f_, gg, o_;
            gates4_f(ai0, ai1, ai2, ai3, addv, lane, i_, f_, gg, o_);
            if (lane == 0) {
                c1 = f_ * c1 + i_ * gg;
                g_d1f[unit] = o_ * tanhf(c1);
            }
        }
        gbar(bar, epoch);
        // ---- phase C: Whh1@h1 precompute + bf16 projection (L2-resident __ldg) ----
        if (tid < 256)
            *(float4*)(sh1 + tid * 4) = __ldcg((const float4*)(&g_d1f[tid * 4]));
        __syncthreads();
        if (unit < HSZ) {
            ah1p0 = 0; ah1p1 = 0; ah1p2 = 0; ah1p3 = 0;
            const float* bh1 = dWhh1 + (size_t)unit * 1024;
#pragma unroll
            for (int k = 0; k < 8; k++) {
                int j = (k * 32 + lane) << 2;
                float4 h4 = *(float4*)(sh1 + j);
                float4 w;
                w = __ldg((const float4*)(bh1 + j));
                ah1p0 += w.x * h4.x + w.y * h4.y + w.z * h4.z + w.w * h4.w;
                w = __ldg((const float4*)(bh1 + (1 << 20) + j));
                ah1p1 += w.x * h4.x + w.y * h4.y + w.z * h4.z + w.w * h4.w;
                w = __ldg((const float4*)(bh1 + (2 << 20) + j));
                ah1p2 += w.x * h4.x + w.y * h4.y + w.z * h4.z + w.w * h4.w;
                w = __ldg((const float4*)(bh1 + (3 << 20) + j));
                ah1p3 += w.x * h4.x + w.y * h4.y + w.z * h4.z + w.w * h4.w;
            }
            ah1p0 = wredsum(ah1p0); ah1p1 = wredsum(ah1p1);
            ah1p2 = wredsum(ah1p2); ah1p3 = wredsum(ah1p3);
        }
        float bestv = -INFINITY; int besti = 0;
        float* orow = out + (size_t)(t + 1) * VSZ;
        int r = gw;
        int nlg = 0;
        for (; r + nw < VSZ; r += 2 * nw) {
            int r2 = r + nw;
            const uint4* wr0 = (const uint4*)(g_owbf + (size_t)r * 512);
            const uint4* wr1 = (const uint4*)(g_owbf + (size_t)r2 * 512);
            float pA0 = 0, pA1 = 0, pB0 = 0, pB1 = 0;
#pragma unroll
            for (int k = 0; k < 4; k++) {
                int q = k * 32 + lane;
                uint4 wa = __ldg(wr0 + q);      // L2-resident (no evict-first)
                uint4 wb = __ldg(wr1 + q);
                float4 h0 = *(float4*)(sh1 + 8 * q);
                float4 h1 = *(float4*)(sh1 + 8 * q + 4);
                pA0 += bflo(wa.x) * h0.x + bfhi(wa.x) * h0.y + bflo(wa.y) * h0.z + bfhi(wa.y) * h0.w;
                pA1 += bflo(wa.z) * h1.x + bfhi(wa.z) * h1.y + bflo(wa.w) * h1.z + bfhi(wa.w) * h1.w;
                pB0 += bflo(wb.x) * h0.x + bfhi(wb.x) * h0.y + bflo(wb.y) * h0.z + bfhi(wb.y) * h0.w;
                pB1 += bflo(wb.z) * h1.x + bfhi(wb.z) * h1.y + bflo(wb.w) * h1.z + bfhi(wb.w) * h1.w;
            }
            float accA = wredsum(pA0 + pA1);
            float accB = wredsum(pB0 + pB1);
            if (lane == 0) {
                float lgA = accA + __ldg(outb + r);
                float lgB = accB + __ldg(outb + r2);
                orow[r] = lgA;
                orow[r2] = lgB;
                slg[wid][nlg] = lgA;
                slg[wid][nlg + 1] = lgB;
                if (lgA > bestv) { bestv = lgA; besti = r; }
                if (lgB > bestv) { bestv = lgB; besti = r2; }
            }
            nlg += 2;
        }
        if (r < VSZ) {
            const uint4* wr0 = (const uint4*)(g_owbf + (size_t)r * 512);
            float p0 = 0, p1 = 0;
#pragma unroll
            for (int k = 0; k < 4; k++) {
                int q = k * 32 + lane;
                uint4 wa = __ldg(wr0 + q);
                float4 h0 = *(float4*)(sh1 + 8 * q);
                float4 h1 = *(float4*)(sh1 + 8 * q + 4);
                p0 += bflo(wa.x) * h0.x + bfhi(wa.x) * h0.y + bflo(wa.y) * h0.z + bfhi(wa.y) * h0.w;
                p1 += bflo(wa.z) * h1.x + bfhi(wa.z) * h1.y + bflo(wa.w) * h1.z + bfhi(wa.w) * h1.w;
            }
            float acc = wredsum(p0 + p1);
            if (lane == 0) {
                float lg = acc + __ldg(outb + r);
                orow[r] = lg;
                slg[wid][nlg] = lg;
                if (lg > bestv) { bestv = lg; besti = r; }
            }
        }
        __syncwarp();
        // ---- fp32 rescue vs warp-local best, logits replayed from SMEM stash ----
        {
            float thresh = __shfl_sync(0xffffffffu, bestv, 0) - MARGIN;
            unsigned long long bkey2 = 0ull;
            int rr = gw, k = 0;
            for (; rr + nw < VSZ; rr += 2 * nw, k += 2) {
#pragma unroll
                for (int s = 0; s < 2; s++) {
                    float lv = slg[wid][k + s];
                    int rx = rr + s * nw;
                    if (lv >= thresh) {
                        const float* wrf = outw + (size_t)rx * 1024;
                        float p0 = 0, p1 = 0;
#pragma unroll
                        for (int kk = 0; kk < 8; kk += 2) {
                            int j0 = (kk * 32 + lane) << 2;
                            int j1 = ((kk + 1) * 32 + lane) << 2;
                            float4 wa0 = __ldg((const float4*)(wrf + j0));
                            float4 wa1 = __ldg((const float4*)(wrf + j1));
                            float4 h40 = *(float4*)(sh1 + j0);
                            float4 h41 = *(float4*)(sh1 + j1);
                            p0 += wa0.x * h40.x + wa0.y * h40.y + wa0.z * h40.z + wa0.w * h40.w;
                            p1 += wa1.x * h41.x + wa1.y * h41.y + wa1.z * h41.z + wa1.w * h41.w;
                        }
                        float accf = wredsum(p0 + p1);
                        if (lane == 0) {
                            float lgf = accf + __ldg(outb + rx);
                            orow[rx] = lgf;
                            unsigned long long kx = mkkey(lgf, rx);
                            if (kx > bkey2) bkey2 = kx;
                        }
                    }
                }
            }
            if (rr < VSZ) {
                float lv = slg[wid][k];
                if (lv >= thresh) {
                    const float* wrf = outw + (size_t)rr * 1024;
                    float p0 = 0, p1 = 0;
#pragma unroll
                    for (int kk = 0; kk < 8; kk += 2) {
                        int j0 = (kk * 32 + lane) << 2;
                        int j1 = ((kk + 1) * 32 + lane) << 2;
                        float4 wa0 = __ldg((const float4*)(wrf + j0));
                        float4 wa1 = __ldg((const float4*)(wrf + j1));
                        float4 h40 = *(float4*)(sh1 + j0);
                        float4 h41 = *(float4*)(sh1 + j1);
                        p0 += wa0.x * h40.x + wa0.y * h40.y + wa0.z * h40.z + wa0.w * h40.w;
                        p1 += wa1.x * h41.x + wa1.y * h41.y + wa1.z * h41.z + wa1.w * h41.w;
                    }
                    float accf = wredsum(p0 + p1);
                    if (lane == 0) {
                        float lgf = accf + __ldg(outb + rr);
                        orow[rr] = lgf;
                        unsigned long long kx = mkkey(lgf, rr);
                        if (kx > bkey2) bkey2 = kx;
                    }
                }
            }
            if (lane == 0) skeys[wid] = bkey2;
        }
        __syncthreads();
        if (tid == 0) {
            unsigned long long k0 = skeys[0];
#pragma unroll
            for (int w = 1; w < 16; w++) if (skeys[w] > k0) k0 = skeys[w];
            atomicMax(&g_amax[t], k0);
        }
        gbar(bar, epoch);
    }
}

// ---------------- final log_softmax over rows (in place) ----------------
__global__ void logsoftmax_kernel(float* __restrict__ out) {
    int row = blockIdx.x, tid = threadIdx.x, wid = tid >> 5, lane = tid & 31;
    float* p = out + (size_t)row * VSZ;
    if (row == 0) {
        float v = -(float)log((double)VSZ);
        for (int i = tid; i < VSZ; i += blockDim.x) p[i] = v;
        return;
    }
    __shared__ double redd[8];
    __shared__ float redf[8];
    __shared__ float bcf;
    __shared__ double bcd;
    float m = -INFINITY;
    for (int i = tid; i < VSZ; i += blockDim.x) m = fmaxf(m, p[i]);
#pragma unroll
    for (int o = 16; o; o >>= 1) m = fmaxf(m, __shfl_xor_sync(0xffffffffu, m, o));
    if (lane == 0) redf[wid] = m;
    __syncthreads();
    if (tid == 0) {
        float mm = redf[0];
#pragma unroll
        for (int i = 1; i < 8; i++) mm = fmaxf(mm, redf[i]);
        bcf = mm;
    }
    __syncthreads();
    m = bcf;
    double s = 0;
    for (int i = tid; i < VSZ; i += blockDim.x) s += (double)expf(p[i] - m);
    s = wredsum_d(s);
    if (lane == 0) redd[wid] = s;
    __syncthreads();
    if (tid == 0) {
        double ss = 0;
#pragma unroll
        for (int i = 0; i < 8; i++) ss += redd[i];
        bcd = (double)m + log(ss);
    }
    __syncthreads();
    double lse = bcd;
    for (int i = tid; i < VSZ; i += blockDim.x) p[i] = (float)((double)p[i] - lse);
}

// ---------------- launch ----------------
extern "C" void kernel_launch(void* const* d_in, const int* in_sizes, int n_in,
                              void* d_out, int out_size) {
    const int*   x     = (const int*)d_in[0];
    const int*   y     = (const int*)d_in[1];
    const float* emb   = (const float*)d_in[2];
    const float* eWih0 = (const float*)d_in[3];
    const float* eWhh0 = (const float*)d_in[4];
    const float* eb0   = (const float*)d_in[5];
    const float* eWih1 = (const float*)d_in[6];
    const float* eWhh1 = (const float*)d_in[7];
    const float* eb1   = (const float*)d_in[8];
    const float* fc1w  = (const float*)d_in[9];
    const float* fc1b  = (const float*)d_in[10];
    const float* fc2w  = (const float*)d_in[11];
    const float* fc2b  = (const float*)d_in[12];
    const float* dWih0 = (const float*)d_in[13];
    const float* dWhh0 = (const float*)d_in[14];
    const float* db0   = (const float*)d_in[15];
    const float* dWih1 = (const float*)d_in[16];
    const float* dWhh1 = (const float*)d_in[17];
    const float* db1   = (const float*)d_in[18];
    const float* outw  = (const float*)d_in[19];
    const float* outb  = (const float*)d_in[20];
    float* out = (float*)d_out;

    float *pG = nullptr, *pSeq = nullptr, *pF1 = nullptr, *pHinit = nullptr, *pHlast = nullptr;
    cudaGetSymbolAddress((void**)&pG, g_G);
    cudaGetSymbolAddress((void**)&pSeq, g_seq);
    cudaGetSymbolAddress((void**)&pF1, g_f1);
    cudaGetSymbolAddress((void**)&pHinit, g_hinit);
    cudaGetSymbolAddress((void**)&pHlast, g_hlast);

    int dev = 0, nsm = 148;
    cudaGetDevice(&dev);
    cudaDeviceGetAttribute(&nsm, cudaDevAttrMultiProcessorCount, dev);
    if (nsm < 128) nsm = 128;

    init_kernel<<<1, 512>>>();
    conv_bf16<<<VSZ * (HSZ / 4) / 256, 256>>>(outw);
    gemm_nt<ESZ><<<dim3(64, 32), 256>>>(emb, x, eWih0, eb0, pG);
    enc_scan<1, 0, 0><<<128, 512>>>(eWhh0, pG, pSeq);
    gemm_nt<HSZ><<<dim3(64, 32), 256>>>(pSeq, nullptr, eWih1, eb1, pG);
    enc_scan<0, 1, 1><<<128, 512>>>(eWhh1, pG, nullptr);
    fc_relu<<<1024, 256>>>(fc1w, fc1b, pHlast, pF1);
    fc_relu<<<1024, 256>>>(fc2w, fc2b, pF1, pHinit);
    decoder_kernel<<<nsm, DECT>>>(dWih0, dWhh0, db0, dWih1, dWhh1, db1, outw, outb, y, out);
    logsoftmax_kernel<<<TYN, 256>>>(out);
}

// round 16
// speedup vs baseline: 1.1900x; 1.1900x over previous
#include <cuda_runtime.h>
#include <cuda_bf16.h>
#include <math.h>

// ---------------- problem constants ----------------
#define VSZ   32000
#define ESZ   512
#define HSZ   1024
#define TXN   2048
#define TYN   512
#define G4    4096
#define MARGIN 0.03f

// ---------------- device scratch ----------------
// G layout: [blk(128)][t(2048)][gate(4)][ui(8)]
__device__ float g_G[(size_t)TXN * G4];
__device__ float g_seq[(size_t)TXN * HSZ];
__device__ unsigned g_owbf[(size_t)VSZ * HSZ / 2];   // bf16 out_w (65.5MB)
__device__ float g_h[2][HSZ];
__device__ float g_hlast[HSZ];
__device__ float g_f1[HSZ];
__device__ float g_hinit[HSZ];
__device__ float g_aw0[2][G4];
__device__ float g_d1f[HSZ];
__device__ unsigned long long g_amax[TYN - 1];
__device__ unsigned int g_bars[4];

// ---------------- helpers ----------------
__device__ __forceinline__ float wredsum(float v) {
#pragma unroll
    for (int o = 16; o; o >>= 1) v += __shfl_xor_sync(0xffffffffu, v, o);
    return v;
}
__device__ __forceinline__ double wredsum_d(double v) {
#pragma unroll
    for (int o = 16; o; o >>= 1) v += __shfl_xor_sync(0xffffffffu, v, o);
    return v;
}
__device__ __forceinline__ float bflo(unsigned u) { return __uint_as_float(u << 16); }
__device__ __forceinline__ float bfhi(unsigned u) { return __uint_as_float(u & 0xFFFF0000u); }

__device__ __forceinline__ unsigned long long mkkey(float v, int idx) {
    unsigned u = __float_as_uint(v);
    u = (u & 0x80000000u) ? ~u : (u | 0x80000000u);
    return ((unsigned long long)u << 32) |
           (unsigned long long)(0xFFFFFFFFu - (unsigned)idx);
}

__device__ __forceinline__ void gates4_f(float a0, float a1, float a2, float a3,
                                         float addv, int lane,
                                         float& i_, float& f_, float& g_, float& o_) {
    float asel = (lane == 0) ? a0 : (lane == 1) ? a1 : (lane == 2) ? a2 : a3;
    float gv = 0.0f;
    if (lane < 4) {
        float x = asel + addv;
        gv = (lane == 2) ? tanhf(x) : 1.0f / (1.0f + expf(-x));
    }
    i_ = __shfl_sync(0xffffffffu, gv, 0);
    f_ = __shfl_sync(0xffffffffu, gv, 1);
    g_ = __shfl_sync(0xffffffffu, gv, 2);
    o_ = __shfl_sync(0xffffffffu, gv, 3);
}

// release/acquire software grid barrier (single counter)
__device__ __forceinline__ void gbar(unsigned int* cnt, unsigned int& epoch) {
    epoch += gridDim.x;
    __syncthreads();
    if (threadIdx.x == 0) {
        asm volatile("red.release.gpu.global.add.u32 [%0], %1;"
                     :: "l"(cnt), "r"(1u) : "memory");
        unsigned cur;
        do {
            asm volatile("ld.acquire.gpu.global.u32 %0, [%1];"
                         : "=r"(cur) : "l"(cnt) : "memory");
        } while ((int)(cur - epoch) < 0);
    }
    __syncthreads();
}

// ---------------- init ----------------
__global__ void init_kernel() {
    int i = threadIdx.x;
    if (i < 4) g_bars[i] = 0u;
    for (int j = i; j < TYN - 1; j += blockDim.x) g_amax[j] = 0ull;
}

// ---------------- out_w fp32 -> bf16 (one-time) ----------------
__global__ void conv_bf16(const float* __restrict__ w) {
    size_t i = (size_t)blockIdx.x * blockDim.x + threadIdx.x;
    float4 v = *(const float4*)(w + i * 4);
    unsigned b0 = (unsigned)__bfloat16_as_ushort(__float2bfloat16_rn(v.x)) |
                  ((unsigned)__bfloat16_as_ushort(__float2bfloat16_rn(v.y)) << 16);
    unsigned b1 = (unsigned)__bfloat16_as_ushort(__float2bfloat16_rn(v.z)) |
                  ((unsigned)__bfloat16_as_ushort(__float2bfloat16_rn(v.w)) << 16);
    g_owbf[i * 2] = b0;
    g_owbf[i * 2 + 1] = b1;
}

// ---------------- tiled GEMM (fp32) with block-major transposed output ----------------
template <int KDIM>
__global__ void gemm_nt(const float* __restrict__ A, const int* __restrict__ ridx,
                        const float* __restrict__ B, const float* __restrict__ bias,
                        float* __restrict__ C) {
    __shared__ float As[64][17];
    __shared__ float Bs[64][17];
    int tid = threadIdx.x;
    int m0 = blockIdx.y * 64, n0 = blockIdx.x * 64;
    int tx = tid & 15, ty = tid >> 4;
    int lrow = tid >> 2;
    int lk4 = (tid & 3) * 4;
    const float* arow = A + (size_t)(ridx ? ridx[m0 + lrow] : (m0 + lrow)) * KDIM;
    const float* brow = B + (size_t)(n0 + lrow) * KDIM;
    float acc[4][4] = {};
    for (int kb = 0; kb < KDIM; kb += 16) {
        float4 av = *(const float4*)(arow + kb + lk4);
        float4 bv = *(const float4*)(brow + kb + lk4);
        __syncthreads();
        As[lrow][lk4 + 0] = av.x; As[lrow][lk4 + 1] = av.y;
        As[lrow][lk4 + 2] = av.z; As[lrow][lk4 + 3] = av.w;
        Bs[lrow][lk4 + 0] = bv.x; Bs[lrow][lk4 + 1] = bv.y;
        Bs[lrow][lk4 + 2] = bv.z; Bs[lrow][lk4 + 3] = bv.w;
        __syncthreads();
#pragma unroll
        for (int kk = 0; kk < 16; kk++) {
            float a[4], b[4];
#pragma unroll
            for (int i = 0; i < 4; i++) a[i] = As[ty * 4 + i][kk];
#pragma unroll
            for (int j = 0; j < 4; j++) b[j] = Bs[tx * 4 + j][kk];
#pragma unroll
            for (int i = 0; i < 4; i++)
#pragma unroll
                for (int j = 0; j < 4; j++) acc[i][j] += a[i] * b[j];
        }
    }
    int nb = n0 + tx * 4;
    int gate = nb >> 10;
    int u = nb & 1023;
    int blk = u >> 3, ui = u & 7;
    float4 b4 = __ldg((const float4*)(bias + nb));
    float* cb = C + (size_t)blk * (TXN * 32) + gate * 8 + ui;
#pragma unroll
    for (int i = 0; i < 4; i++) {
        int m = m0 + ty * 4 + i;
        float4 v = make_float4(acc[i][0] + b4.x, acc[i][1] + b4.y,
                               acc[i][2] + b4.z, acc[i][3] + b4.w);
        *(float4*)(cb + (size_t)m * 32) = v;
    }
}

// ---------------- persistent encoder LSTM scan — register-resident Whh (R12) ----------------
template <int WRITE_SEQ, int WRITE_LAST, int BARIDX>
__global__ void __launch_bounds__(512, 1)
enc_scan(const float* __restrict__ Whh, const float* __restrict__ G,
         float* __restrict__ seq) {
    __shared__ float sh[HSZ];
    __shared__ float spart[8][4];
    int tid = threadIdx.x, w = tid >> 5, lane = tid & 31;
    int ui = w >> 1, half = w & 1;
    int unit = blockIdx.x * 8 + ui;
    float4 wr[4][4];
#pragma unroll
    for (int g = 0; g < 4; g++) {
        const float* bg = Whh + (size_t)(g * 1024 + unit) * 1024 + half * 512;
#pragma unroll
        for (int j = 0; j < 4; j++)
            wr[g][j] = __ldg((const float4*)(bg + j * 128 + lane * 4));
    }
    if (blockIdx.x == 0)
        for (int i = tid; i < HSZ; i += blockDim.x) g_h[0][i] = 0.0f;
    unsigned int epoch = 0;
    unsigned int* bar = &g_bars[BARIDX];
    const float* gp = G + (size_t)blockIdx.x * (TXN * 32);
    gbar(bar, epoch);
    float c = 0.0f;
    int cur = 0;
    for (int t = 0; t < TXN; t++) {
        float addv = 0.0f;
        if (half == 0 && lane < 4) addv = __ldg(gp + t * 32 + lane * 8 + ui);
        if (tid == 256 && t + 16 < TXN)
            asm volatile("prefetch.global.L2 [%0];" :: "l"(gp + (t + 16) * 32));
        if (tid < 256)
            *(float4*)(sh + tid * 4) = __ldcg((const float4*)(&g_h[cur][tid * 4]));
        __syncthreads();
        float4 h4[4];
#pragma unroll
        for (int j = 0; j < 4; j++)
            h4[j] = *(float4*)(sh + half * 512 + j * 128 + lane * 4);
        float a0 = 0, a1 = 0, a2 = 0, a3 = 0;
#pragma unroll
        for (int j = 0; j < 4; j++) {
            a0 += wr[0][j].x * h4[j].x + wr[0][j].y * h4[j].y +
                  wr[0][j].z * h4[j].z + wr[0][j].w * h4[j].w;
            a1 += wr[1][j].x * h4[j].x + wr[1][j].y * h4[j].y +
                  wr[1][j].z * h4[j].z + wr[1][j].w * h4[j].w;
            a2 += wr[2][j].x * h4[j].x + wr[2][j].y * h4[j].y +
                  wr[2][j].z * h4[j].z + wr[2][j].w * h4[j].w;
            a3 += wr[3][j].x * h4[j].x + wr[3][j].y * h4[j].y +
                  wr[3][j].z * h4[j].z + wr[3][j].w * h4[j].w;
        }
        a0 = wredsum(a0); a1 = wredsum(a1); a2 = wredsum(a2); a3 = wredsum(a3);
        float asel = (lane == 0) ? a0 : (lane == 1) ? a1 : (lane == 2) ? a2 : a3;
        if (half == 1 && lane < 4) spart[ui][lane] = asel;
        __syncthreads();
        if (half == 0) {
            float gv = 0.0f;
            if (lane < 4) {
                float x = asel + spart[ui][lane] + addv;
                gv = (lane == 2) ? tanhf(x) : 1.0f / (1.0f + expf(-x));
            }
            float i_ = __shfl_sync(0xffffffffu, gv, 0);
            float f_ = __shfl_sync(0xffffffffu, gv, 1);
            float gg = __shfl_sync(0xffffffffu, gv, 2);
            float o_ = __shfl_sync(0xffffffffu, gv, 3);
            if (lane == 0) {
                c = f_ * c + i_ * gg;
                float h = o_ * tanhf(c);
                g_h[cur ^ 1][unit] = h;
                if (WRITE_SEQ) seq[(size_t)t * HSZ + unit] = h;
                if (WRITE_LAST && t == TXN - 1) g_hlast[unit] = h;
            }
        }
        gbar(bar, epoch);
        cur ^= 1;
    }
}

// ---------------- fc + relu (fp64, off hot path) ----------------
__global__ void fc_relu(const float* __restrict__ W, const float* __restrict__ b,
                        const float* __restrict__ in, float* __restrict__ out) {
    __shared__ double red[8];
    int r = blockIdx.x, tid = threadIdx.x, wid = tid >> 5, lane = tid & 31;
    const float* wr = W + (size_t)r * 1024;
    float4 w = __ldg((const float4*)(wr + tid * 4));
    float4 v = __ldg((const float4*)(in + tid * 4));
    double acc = (double)(w.x * v.x) + (double)(w.y * v.y) +
                 (double)(w.z * v.z) + (double)(w.w * v.w);
    acc = wredsum_d(acc);
    if (lane == 0) red[wid] = acc;
    __syncthreads();
    if (tid == 0) {
        double s = 0;
#pragma unroll
        for (int i = 0; i < 8; i++) s += red[i];
        double val = s + (double)__ldg(b + r);
        out[r] = (float)(val > 0.0 ? val : 0.0);
    }
}

// ---------------- persistent greedy decoder (R12 + SMEM logit stash) ----------------
#define DECT 512
__global__ void __launch_bounds__(DECT, 1)
decoder_kernel(
    const float* __restrict__ dWih0, const float* __restrict__ dWhh0, const float* __restrict__ db0,
    const float* __restrict__ dWih1, const float* __restrict__ dWhh1, const float* __restrict__ db1,
    const float* __restrict__ outw, const float* __restrict__ outb,
    const int* __restrict__ y, float* __restrict__ out) {
    __shared__ float sh0[HSZ];
    __shared__ float sh1[HSZ];
    __shared__ float c0s[HSZ];
    __shared__ float wih0s[G4];
    __shared__ float b0s[G4];
    __shared__ float slg[16][16];                 // per-warp phase-A logit stash
    __shared__ unsigned long long skeys[16];
    int tid = threadIdx.x, wid = tid >> 5, lane = tid & 31;
    int unit = wid * gridDim.x + blockIdx.x;
    unsigned int epoch = 0;
    unsigned int* bar = &g_bars[2];

    for (int i = tid; i < G4; i += DECT) {
        wih0s[i] = __ldg(dWih0 + i);
        b0s[i] = __ldg(db0 + i);
    }
    for (int i = tid; i < HSZ; i += DECT) {
        float v = __ldg(&g_hinit[i]);
        c0s[i] = v;
        sh0[i] = v;
    }
    __syncthreads();

    float c1 = 0.0f;
    if (unit < HSZ) c1 = __ldg(&g_hinit[unit]);

    float ah1p0 = 0, ah1p1 = 0, ah1p2 = 0, ah1p3 = 0;
    if (unit < HSZ) {
        float w0 = 0, w1 = 0, w2 = 0, w3 = 0;
        const float* bh0 = dWhh0 + (size_t)unit * 1024;
        const float* bh1 = dWhh1 + (size_t)unit * 1024;
#pragma unroll
        for (int k = 0; k < 8; k++) {
            int j = (k * 32 + lane) << 2;
            float4 h4 = *(float4*)(sh0 + j);
            float4 w;
            w = __ldg((const float4*)(bh0 + j));
            w0 += w.x * h4.x + w.y * h4.y + w.z * h4.z + w.w * h4.w;
            w = __ldg((const float4*)(bh0 + (1 << 20) + j));
            w1 += w.x * h4.x + w.y * h4.y + w.z * h4.z + w.w * h4.w;
            w = __ldg((const float4*)(bh0 + (2 << 20) + j));
            w2 += w.x * h4.x + w.y * h4.y + w.z * h4.z + w.w * h4.w;
            w = __ldg((const float4*)(bh0 + (3 << 20) + j));
            w3 += w.x * h4.x + w.y * h4.y + w.z * h4.z + w.w * h4.w;
            w = __ldg((const float4*)(bh1 + j));
            ah1p0 += w.x * h4.x + w.y * h4.y + w.z * h4.z + w.w * h4.w;
            w = __ldg((const float4*)(bh1 + (1 << 20) + j));
            ah1p1 += w.x * h4.x + w.y * h4.y + w.z * h4.z + w.w * h4.w;
            w = __ldg((const float4*)(bh1 + (2 << 20) + j));
            ah1p2 += w.x * h4.x + w.y * h4.y + w.z * h4.z + w.w * h4.w;
            w = __ldg((const float4*)(bh1 + (3 << 20) + j));
            ah1p3 += w.x * h4.x + w.y * h4.y + w.z * h4.z + w.w * h4.w;
        }
        w0 = wredsum(w0); w1 = wredsum(w1); w2 = wredsum(w2); w3 = wredsum(w3);
        ah1p0 = wredsum(ah1p0); ah1p1 = wredsum(ah1p1);
        ah1p2 = wredsum(ah1p2); ah1p3 = wredsum(ah1p3);
        float wsel = (lane == 0) ? w0 : (lane == 1) ? w1 : (lane == 2) ? w2 : w3;
        if (lane < 4) g_aw0[0][lane * 1024 + unit] = wsel;
    }
    gbar(bar, epoch);

    float xt0 = (float)__ldg(&y[0]);
    int gw = blockIdx.x * 16 + wid, nw = gridDim.x * 16;

    for (int t = 0; t < TYN - 1; t++) {
        float xt;
        if (t == 0) xt = xt0;
        else {
            unsigned long long key = __ldcg(&g_amax[t - 1]);
            xt = (float)(0xFFFFFFFFu - (unsigned int)(key & 0xFFFFFFFFull));
        }
        // ---- phase A: replicated layer0 ----
        {
            const float* aw = &g_aw0[t & 1][0];
#pragma unroll
            for (int uu = 0; uu < 2; uu++) {
                int u = tid + uu * DECT;
                float x0 = __ldcg(aw + u)        + (wih0s[u] * xt        + b0s[u]);
                float x1 = __ldcg(aw + 1024 + u) + (wih0s[1024 + u] * xt + b0s[1024 + u]);
                float x2 = __ldcg(aw + 2048 + u) + (wih0s[2048 + u] * xt + b0s[2048 + u]);
                float x3 = __ldcg(aw + 3072 + u) + (wih0s[3072 + u] * xt + b0s[3072 + u]);
                float i_ = 1.0f / (1.0f + expf(-x0));
                float f_ = 1.0f / (1.0f + expf(-x1));
                float gg = tanhf(x2);
                float o_ = 1.0f / (1.0f + expf(-x3));
                float c = f_ * c0s[u] + i_ * gg;
                c0s[u] = c;
                sh0[u] = o_ * tanhf(c);
            }
        }
        __syncthreads();
        // ---- phase B ----
        if (unit < HSZ) {
            float ai0 = 0, ai1 = 0, ai2 = 0, ai3 = 0;
            float w0 = 0, w1 = 0, w2 = 0, w3 = 0;
            const float* bi = dWih1 + (size_t)unit * 1024;
            const float* bh0 = dWhh0 + (size_t)unit * 1024;
#pragma unroll
            for (int k = 0; k < 8; k++) {
                int j = (k * 32 + lane) << 2;
                float4 h4 = *(float4*)(sh0 + j);
                float4 w;
                w = __ldg((const float4*)(bi + j));
                ai0 += w.x * h4.x + w.y * h4.y + w.z * h4.z + w.w * h4.w;
                w = __ldg((const float4*)(bi + (1 << 20) + j));
                ai1 += w.x * h4.x + w.y * h4.y + w.z * h4.z + w.w * h4.w;
                w = __ldg((const float4*)(bi + (2 << 20) + j));
                ai2 += w.x * h4.x + w.y * h4.y + w.z * h4.z + w.w * h4.w;
                w = __ldg((const float4*)(bi + (3 << 20) + j));
                ai3 += w.x * h4.x + w.y * h4.y + w.z * h4.z + w.w * h4.w;
                w = __ldg((const float4*)(bh0 + j));
                w0 += w.x * h4.x + w.y * h4.y + w.z * h4.z + w.w * h4.w;
                w = __ldg((const float4*)(bh0 + (1 << 20) + j));
                w1 += w.x * h4.x + w.y * h4.y + w.z * h4.z + w.w * h4.w;
                w = __ldg((const float4*)(bh0 + (2 << 20) + j));
                w2 += w.x * h4.x + w.y * h4.y + w.z * h4.z + w.w * h4.w;
                w = __ldg((const float4*)(bh0 + (3 << 20) + j));
                w3 += w.x * h4.x + w.y * h4.y + w.z * h4.z + w.w * h4.w;
            }
            ai0 = wredsum(ai0); ai1 = wredsum(ai1); ai2 = wredsum(ai2); ai3 = wredsum(ai3);
            w0 = wredsum(w0); w1 = wredsum(w1); w2 = wredsum(w2); w3 = wredsum(w3);
            float wsel = (lane == 0) ? w0 : (lane == 1) ? w1 : (lane == 2) ? w2 : w3;
            if (lane < 4) g_aw0[(t + 1) & 1][lane * 1024 + unit] = wsel;
            float addv = 0.0f;
            if (lane < 4) {
                float ap = (lane == 0) ? ah1p0 : (lane == 1) ? ah1p1
                         : (lane == 2) ? ah1p2 : ah1p3;
                addv = ap + __ldg(db1 + unit + lane * 1024);
            }
            float i_, f_, gg, o_;
            gates4_f(ai0, ai1, ai2, ai3, addv, lane, i_, f_, gg, o_);
            if (lane == 0) {
                c1 = f_ * c1 + i_ * gg;
                g_d1f[unit] = o_ * tanhf(c1);
            }
        }
        gbar(bar, epoch);
        // ---- phase C: Whh1@h1 precompute + bf16 projection (__ldcs streaming) ----
        if (tid < 256)
            *(float4*)(sh1 + tid * 4) = __ldcg((const float4*)(&g_d1f[tid * 4]));
        __syncthreads();
        if (unit < HSZ) {
            ah1p0 = 0; ah1p1 = 0; ah1p2 = 0; ah1p3 = 0;
            const float* bh1 = dWhh1 + (size_t)unit * 1024;
#pragma unroll
            for (int k = 0; k < 8; k++) {
                int j = (k * 32 + lane) << 2;
                float4 h4 = *(float4*)(sh1 + j);
                float4 w;
                w = __ldg((const float4*)(bh1 + j));
                ah1p0 += w.x * h4.x + w.y * h4.y + w.z * h4.z + w.w * h4.w;
                w = __ldg((const float4*)(bh1 + (1 << 20) + j));
                ah1p1 += w.x * h4.x + w.y * h4.y + w.z * h4.z + w.w * h4.w;
                w = __ldg((const float4*)(bh1 + (2 << 20) + j));
                ah1p2 += w.x * h4.x + w.y * h4.y + w.z * h4.z + w.w * h4.w;
                w = __ldg((const float4*)(bh1 + (3 << 20) + j));
                ah1p3 += w.x * h4.x + w.y * h4.y + w.z * h4.z + w.w * h4.w;
            }
            ah1p0 = wredsum(ah1p0); ah1p1 = wredsum(ah1p1);
            ah1p2 = wredsum(ah1p2); ah1p3 = wredsum(ah1p3);
        }
        float bestv = -INFINITY; int besti = 0;
        float* orow = out + (size_t)(t + 1) * VSZ;
        int r = gw;
        int nlg = 0;
        for (; r + nw < VSZ; r += 2 * nw) {
            int r2 = r + nw;
            const uint4* wr0 = (const uint4*)(g_owbf + (size_t)r * 512);
            const uint4* wr1 = (const uint4*)(g_owbf + (size_t)r2 * 512);
            float pA0 = 0, pA1 = 0, pB0 = 0, pB1 = 0;
#pragma unroll
            for (int k = 0; k < 4; k++) {
                int q = k * 32 + lane;
                uint4 wa = __ldcs(wr0 + q);      // streaming: protect LSTM weights in L2
                uint4 wb = __ldcs(wr1 + q);
                float4 h0 = *(float4*)(sh1 + 8 * q);
                float4 h1 = *(float4*)(sh1 + 8 * q + 4);
                pA0 += bflo(wa.x) * h0.x + bfhi(wa.x) * h0.y + bflo(wa.y) * h0.z + bfhi(wa.y) * h0.w;
                pA1 += bflo(wa.z) * h1.x + bfhi(wa.z) * h1.y + bflo(wa.w) * h1.z + bfhi(wa.w) * h1.w;
                pB0 += bflo(wb.x) * h0.x + bfhi(wb.x) * h0.y + bflo(wb.y) * h0.z + bfhi(wb.y) * h0.w;
                pB1 += bflo(wb.z) * h1.x + bfhi(wb.z) * h1.y + bflo(wb.w) * h1.z + bfhi(wb.w) * h1.w;
            }
            float accA = wredsum(pA0 + pA1);
            float accB = wredsum(pB0 + pB1);
            if (lane == 0) {
                float lgA = accA + __ldg(outb + r);
                float lgB = accB + __ldg(outb + r2);
                orow[r] = lgA;
                orow[r2] = lgB;
                slg[wid][nlg] = lgA;
                slg[wid][nlg + 1] = lgB;
                if (lgA > bestv) { bestv = lgA; besti = r; }
                if (lgB > bestv) { bestv = lgB; besti = r2; }
            }
            nlg += 2;
        }
        if (r < VSZ) {
            const uint4* wr0 = (const uint4*)(g_owbf + (size_t)r * 512);
            float p0 = 0, p1 = 0;
#pragma unroll
            for (int k = 0; k < 4; k++) {
                int q = k * 32 + lane;
                uint4 wa = __ldcs(wr0 + q);
                float4 h0 = *(float4*)(sh1 + 8 * q);
                float4 h1 = *(float4*)(sh1 + 8 * q + 4);
                p0 += bflo(wa.x) * h0.x + bfhi(wa.x) * h0.y + bflo(wa.y) * h0.z + bfhi(wa.y) * h0.w;
                p1 += bflo(wa.z) * h1.x + bfhi(wa.z) * h1.y + bflo(wa.w) * h1.z + bfhi(wa.w) * h1.w;
            }
            float acc = wredsum(p0 + p1);
            if (lane == 0) {
                float lg = acc + __ldg(outb + r);
                orow[r] = lg;
                slg[wid][nlg] = lg;
                if (lg > bestv) { bestv = lg; besti = r; }
            }
        }
        __syncwarp();
        // ---- fp32 rescue vs warp-local best, logits replayed from SMEM stash ----
        {
            float thresh = __shfl_sync(0xffffffffu, bestv, 0) - MARGIN;
            unsigned long long bkey2 = 0ull;
            int rr = gw, k = 0;
            for (; rr < VSZ; rr += nw, k++) {
                float lv = slg[wid][k];
                if (lv >= thresh) {
                    const float* wrf = outw + (size_t)rr * 1024;
                    float p0 = 0, p1 = 0;
#pragma unroll
                    for (int kk = 0; kk < 8; kk += 2) {
                        int j0 = (kk * 32 + lane) << 2;
                        int j1 = ((kk + 1) * 32 + lane) << 2;
                        float4 wa0 = __ldg((const float4*)(wrf + j0));
                        float4 wa1 = __ldg((const float4*)(wrf + j1));
                        float4 h40 = *(float4*)(sh1 + j0);
                        float4 h41 = *(float4*)(sh1 + j1);
                        p0 += wa0.x * h40.x + wa0.y * h40.y + wa0.z * h40.z + wa0.w * h40.w;
                        p1 += wa1.x * h41.x + wa1.y * h41.y + wa1.z * h41.z + wa1.w * h41.w;
                    }
                    float accf = wredsum(p0 + p1);
                    if (lane == 0) {
                        float lgf = accf + __ldg(outb + rr);
                        orow[rr] = lgf;
                        unsigned long long kx = mkkey(lgf, rr);
                        if (kx > bkey2) bkey2 = kx;
                    }
                }
            }
            if (lane == 0) skeys[wid] = bkey2;
        }
        __syncthreads();
        if (tid == 0) {
            unsigned long long k0 = skeys[0];
#pragma unroll
            for (int w = 1; w < 16; w++) if (skeys[w] > k0) k0 = skeys[w];
            atomicMax(&g_amax[t], k0);
        }
        gbar(bar, epoch);
    }
}

// ---------------- final log_softmax over rows (in place) ----------------
__global__ void logsoftmax_kernel(float* __restrict__ out) {
    int row = blockIdx.x, tid = threadIdx.x, wid = tid >> 5, lane = tid & 31;
    float* p = out + (size_t)row * VSZ;
    if (row == 0) {
        float v = -(float)log((double)VSZ);
        for (int i = tid; i < VSZ; i += blockDim.x) p[i] = v;
        return;
    }
    __shared__ double redd[8];
    __shared__ float redf[8];
    __shared__ float bcf;
    __shared__ double bcd;
    float m = -INFINITY;
    for (int i = tid; i < VSZ; i += blockDim.x) m = fmaxf(m, p[i]);
#pragma unroll
    for (int o = 16; o; o >>= 1) m = fmaxf(m, __shfl_xor_sync(0xffffffffu, m, o));
    if (lane == 0) redf[wid] = m;
    __syncthreads();
    if (tid == 0) {
        float mm = redf[0];
#pragma unroll
        for (int i = 1; i < 8; i++) mm = fmaxf(mm, redf[i]);
        bcf = mm;
    }
    __syncthreads();
    m = bcf;
    double s = 0;
    for (int i = tid; i < VSZ; i += blockDim.x) s += (double)expf(p[i] - m);
    s = wredsum_d(s);
    if (lane == 0) redd[wid] = s;
    __syncthreads();
    if (tid == 0) {
        double ss = 0;
#pragma unroll
        for (int i = 0; i < 8; i++) ss += redd[i];
        bcd = (double)m + log(ss);
    }
    __syncthreads();
    double lse = bcd;
    for (int i = tid; i < VSZ; i += blockDim.x) p[i] = (float)((double)p[i] - lse);
}

// ---------------- launch ----------------
extern "C" void kernel_launch(void* const* d_in, const int* in_sizes, int n_in,
                              void* d_out, int out_size) {
    const int*   x     = (const int*)d_in[0];
    const int*   y     = (const int*)d_in[1];
    const float* emb   = (const float*)d_in[2];
    const float* eWih0 = (const float*)d_in[3];
    const float* eWhh0 = (const float*)d_in[4];
    const float* eb0   = (const float*)d_in[5];
    const float* eWih1 = (const float*)d_in[6];
    const float* eWhh1 = (const float*)d_in[7];
    const float* eb1   = (const float*)d_in[8];
    const float* fc1w  = (const float*)d_in[9];
    const float* fc1b  = (const float*)d_in[10];
    const float* fc2w  = (const float*)d_in[11];
    const float* fc2b  = (const float*)d_in[12];
    const float* dWih0 = (const float*)d_in[13];
    const float* dWhh0 = (const float*)d_in[14];
    const float* db0   = (const float*)d_in[15];
    const float* dWih1 = (const float*)d_in[16];
    const float* dWhh1 = (const float*)d_in[17];
    const float* db1   = (const float*)d_in[18];
    const float* outw  = (const float*)d_in[19];
    const float* outb  = (const float*)d_in[20];
    float* out = (float*)d_out;

    float *pG = nullptr, *pSeq = nullptr, *pF1 = nullptr, *pHinit = nullptr, *pHlast = nullptr;
    cudaGetSymbolAddress((void**)&pG, g_G);
    cudaGetSymbolAddress((void**)&pSeq, g_seq);
    cudaGetSymbolAddress((void**)&pF1, g_f1);
    cudaGetSymbolAddress((void**)&pHinit, g_hinit);
    cudaGetSymbolAddress((void**)&pHlast, g_hlast);

    int dev = 0, nsm = 148;
    cudaGetDevice(&dev);
    cudaDeviceGetAttribute(&nsm, cudaDevAttrMultiProcessorCount, dev);
    if (nsm < 128) nsm = 128;

    init_kernel<<<1, 512>>>();
    conv_bf16<<<VSZ * (HSZ / 4) / 256, 256>>>(outw);
    gemm_nt<ESZ><<<dim3(64, 32), 256>>>(emb, x, eWih0, eb0, pG);
    enc_scan<1, 0, 0><<<128, 512>>>(eWhh0, pG, pSeq);
    gemm_nt<HSZ><<<dim3(64, 32), 256>>>(pSeq, nullptr, eWih1, eb1, pG);
    enc_scan<0, 1, 1><<<128, 512>>>(eWhh1, pG, nullptr);
    fc_relu<<<1024, 256>>>(fc1w, fc1b, pHlast, pF1);
    fc_relu<<<1024, 256>>>(fc2w, fc2b, pF1, pHinit);
    decoder_kernel<<<nsm, DECT>>>(dWih0, dWhh0, db0, dWih1, dWhh1, db1, outw, outb, y, out);
    logsoftmax_kernel<<<TYN, 256>>>(out);
}

// round 17
// speedup vs baseline: 1.2252x; 1.0295x over previous
#include <cuda_runtime.h>
#include <cuda_bf16.h>
#include <math.h>

// ---------------- problem constants ----------------
#define VSZ   32000
#define ESZ   512
#define HSZ   1024
#define TXN   2048
#define TYN   512
#define G4    4096
#define MARGIN 0.03f

// ---------------- device scratch ----------------
// G layout: [blk(128)][t(2048)][gate(4)][ui(8)]
__device__ float g_G[(size_t)TXN * G4];
__device__ float g_seq[(size_t)TXN * HSZ];
__device__ unsigned g_owi8[(size_t)VSZ * 256];       // int8 out_w (32.75MB), 4/uint
__device__ float g_wsc[VSZ];                         // per-row weight scales
__device__ float g_h[2][HSZ];
__device__ float g_hlast[HSZ];
__device__ float g_f1[HSZ];
__device__ float g_hinit[HSZ];
__device__ float g_aw0[2][G4];
__device__ float g_d1f[HSZ];
__device__ unsigned long long g_amax[TYN - 1];
__device__ unsigned int g_bars[4];

// ---------------- helpers ----------------
__device__ __forceinline__ float wredsum(float v) {
#pragma unroll
    for (int o = 16; o; o >>= 1) v += __shfl_xor_sync(0xffffffffu, v, o);
    return v;
}
__device__ __forceinline__ int wredsum_i(int v) {
#pragma unroll
    for (int o = 16; o; o >>= 1) v += __shfl_xor_sync(0xffffffffu, v, o);
    return v;
}
__device__ __forceinline__ double wredsum_d(double v) {
#pragma unroll
    for (int o = 16; o; o >>= 1) v += __shfl_xor_sync(0xffffffffu, v, o);
    return v;
}
__device__ __forceinline__ float wredmax(float v) {
#pragma unroll
    for (int o = 16; o; o >>= 1) v = fmaxf(v, __shfl_xor_sync(0xffffffffu, v, o));
    return v;
}

__device__ __forceinline__ unsigned long long mkkey(float v, int idx) {
    unsigned u = __float_as_uint(v);
    u = (u & 0x80000000u) ? ~u : (u | 0x80000000u);
    return ((unsigned long long)u << 32) |
           (unsigned long long)(0xFFFFFFFFu - (unsigned)idx);
}

__device__ __forceinline__ void gates4_f(float a0, float a1, float a2, float a3,
                                         float addv, int lane,
                                         float& i_, float& f_, float& g_, float& o_) {
    float asel = (lane == 0) ? a0 : (lane == 1) ? a1 : (lane == 2) ? a2 : a3;
    float gv = 0.0f;
    if (lane < 4) {
        float x = asel + addv;
        gv = (lane == 2) ? tanhf(x) : 1.0f / (1.0f + expf(-x));
    }
    i_ = __shfl_sync(0xffffffffu, gv, 0);
    f_ = __shfl_sync(0xffffffffu, gv, 1);
    g_ = __shfl_sync(0xffffffffu, gv, 2);
    o_ = __shfl_sync(0xffffffffu, gv, 3);
}

// release/acquire software grid barrier (single counter)
__device__ __forceinline__ void gbar(unsigned int* cnt, unsigned int& epoch) {
    epoch += gridDim.x;
    __syncthreads();
    if (threadIdx.x == 0) {
        asm volatile("red.release.gpu.global.add.u32 [%0], %1;"
                     :: "l"(cnt), "r"(1u) : "memory");
        unsigned cur;
        do {
            asm volatile("ld.acquire.gpu.global.u32 %0, [%1];"
                         : "=r"(cur) : "l"(cnt) : "memory");
        } while ((int)(cur - epoch) < 0);
    }
    __syncthreads();
}

__device__ __forceinline__ unsigned pack4i8(float a, float b, float c, float d, float inv) {
    int q0 = __float2int_rn(a * inv) & 0xFF;
    int q1 = __float2int_rn(b * inv) & 0xFF;
    int q2 = __float2int_rn(c * inv) & 0xFF;
    int q3 = __float2int_rn(d * inv) & 0xFF;
    return (unsigned)(q0 | (q1 << 8) | (q2 << 16) | (q3 << 24));
}

// ---------------- init ----------------
__global__ void init_kernel() {
    int i = threadIdx.x;
    if (i < 4) g_bars[i] = 0u;
    for (int j = i; j < TYN - 1; j += blockDim.x) g_amax[j] = 0ull;
}

// ---------------- out_w fp32 -> int8 per-row quantization (one-time) ----------------
__global__ void conv_i8(const float* __restrict__ w) {
    __shared__ float redm[4];
    __shared__ float sinv, ssc;
    int r = blockIdx.x, tid = threadIdx.x, wid = tid >> 5, lane = tid & 31;
    const float* row = w + (size_t)r * 1024;
    float4 v0 = __ldg((const float4*)(row + tid * 8));
    float4 v1 = __ldg((const float4*)(row + tid * 8 + 4));
    float m = fmaxf(fmaxf(fmaxf(fabsf(v0.x), fabsf(v0.y)), fmaxf(fabsf(v0.z), fabsf(v0.w))),
                    fmaxf(fmaxf(fabsf(v1.x), fabsf(v1.y)), fmaxf(fabsf(v1.z), fabsf(v1.w))));
    m = wredmax(m);
    if (lane == 0) redm[wid] = m;
    __syncthreads();
    if (tid == 0) {
        float mm = fmaxf(fmaxf(redm[0], redm[1]), fmaxf(redm[2], redm[3]));
        mm = fmaxf(mm, 1e-20f);
        ssc = mm / 127.0f;
        sinv = 127.0f / mm;
        g_wsc[r] = ssc;
    }
    __syncthreads();
    float inv = sinv;
    unsigned* dst = g_owi8 + (size_t)r * 256 + tid * 2;
    dst[0] = pack4i8(v0.x, v0.y, v0.z, v0.w, inv);
    dst[1] = pack4i8(v1.x, v1.y, v1.z, v1.w, inv);
}

// ---------------- tiled GEMM (fp32) with block-major transposed output ----------------
template <int KDIM>
__global__ void gemm_nt(const float* __restrict__ A, const int* __restrict__ ridx,
                        const float* __restrict__ B, const float* __restrict__ bias,
                        float* __restrict__ C) {
    __shared__ float As[64][17];
    __shared__ float Bs[64][17];
    int tid = threadIdx.x;
    int m0 = blockIdx.y * 64, n0 = blockIdx.x * 64;
    int tx = tid & 15, ty = tid >> 4;
    int lrow = tid >> 2;
    int lk4 = (tid & 3) * 4;
    const float* arow = A + (size_t)(ridx ? ridx[m0 + lrow] : (m0 + lrow)) * KDIM;
    const float* brow = B + (size_t)(n0 + lrow) * KDIM;
    float acc[4][4] = {};
    for (int kb = 0; kb < KDIM; kb += 16) {
        float4 av = *(const float4*)(arow + kb + lk4);
        float4 bv = *(const float4*)(brow + kb + lk4);
        __syncthreads();
        As[lrow][lk4 + 0] = av.x; As[lrow][lk4 + 1] = av.y;
        As[lrow][lk4 + 2] = av.z; As[lrow][lk4 + 3] = av.w;
        Bs[lrow][lk4 + 0] = bv.x; Bs[lrow][lk4 + 1] = bv.y;
        Bs[lrow][lk4 + 2] = bv.z; Bs[lrow][lk4 + 3] = bv.w;
        __syncthreads();
#pragma unroll
        for (int kk = 0; kk < 16; kk++) {
            float a[4], b[4];
#pragma unroll
            for (int i = 0; i < 4; i++) a[i] = As[ty * 4 + i][kk];
#pragma unroll
            for (int j = 0; j < 4; j++) b[j] = Bs[tx * 4 + j][kk];
#pragma unroll
            for (int i = 0; i < 4; i++)
#pragma unroll
                for (int j = 0; j < 4; j++) acc[i][j] += a[i] * b[j];
        }
    }
    int nb = n0 + tx * 4;
    int gate = nb >> 10;
    int u = nb & 1023;
    int blk = u >> 3, ui = u & 7;
    float4 b4 = __ldg((const float4*)(bias + nb));
    float* cb = C + (size_t)blk * (TXN * 32) + gate * 8 + ui;
#pragma unroll
    for (int i = 0; i < 4; i++) {
        int m = m0 + ty * 4 + i;
        float4 v = make_float4(acc[i][0] + b4.x, acc[i][1] + b4.y,
                               acc[i][2] + b4.z, acc[i][3] + b4.w);
        *(float4*)(cb + (size_t)m * 32) = v;
    }
}

// ---------------- persistent encoder LSTM scan — register-resident Whh (R12) ----------------
template <int WRITE_SEQ, int WRITE_LAST, int BARIDX>
__global__ void __launch_bounds__(512, 1)
enc_scan(const float* __restrict__ Whh, const float* __restrict__ G,
         float* __restrict__ seq) {
    __shared__ float sh[HSZ];
    __shared__ float spart[8][4];
    int tid = threadIdx.x, w = tid >> 5, lane = tid & 31;
    int ui = w >> 1, half = w & 1;
    int unit = blockIdx.x * 8 + ui;
    float4 wr[4][4];
#pragma unroll
    for (int g = 0; g < 4; g++) {
        const float* bg = Whh + (size_t)(g * 1024 + unit) * 1024 + half * 512;
#pragma unroll
        for (int j = 0; j < 4; j++)
            wr[g][j] = __ldg((const float4*)(bg + j * 128 + lane * 4));
    }
    if (blockIdx.x == 0)
        for (int i = tid; i < HSZ; i += blockDim.x) g_h[0][i] = 0.0f;
    unsigned int epoch = 0;
    unsigned int* bar = &g_bars[BARIDX];
    const float* gp = G + (size_t)blockIdx.x * (TXN * 32);
    gbar(bar, epoch);
    float c = 0.0f;
    int cur = 0;
    for (int t = 0; t < TXN; t++) {
        float addv = 0.0f;
        if (half == 0 && lane < 4) addv = __ldg(gp + t * 32 + lane * 8 + ui);
        if (tid == 256 && t + 16 < TXN)
            asm volatile("prefetch.global.L2 [%0];" :: "l"(gp + (t + 16) * 32));
        if (tid < 256)
            *(float4*)(sh + tid * 4) = __ldcg((const float4*)(&g_h[cur][tid * 4]));
        __syncthreads();
        float4 h4[4];
#pragma unroll
        for (int j = 0; j < 4; j++)
            h4[j] = *(float4*)(sh + half * 512 + j * 128 + lane * 4);
        float a0 = 0, a1 = 0, a2 = 0, a3 = 0;
#pragma unroll
        for (int j = 0; j < 4; j++) {
            a0 += wr[0][j].x * h4[j].x + wr[0][j].y * h4[j].y +
                  wr[0][j].z * h4[j].z + wr[0][j].w * h4[j].w;
            a1 += wr[1][j].x * h4[j].x + wr[1][j].y * h4[j].y +
                  wr[1][j].z * h4[j].z + wr[1][j].w * h4[j].w;
            a2 += wr[2][j].x * h4[j].x + wr[2][j].y * h4[j].y +
                  wr[2][j].z * h4[j].z + wr[2][j].w * h4[j].w;
            a3 += wr[3][j].x * h4[j].x + wr[3][j].y * h4[j].y +
                  wr[3][j].z * h4[j].z + wr[3][j].w * h4[j].w;
        }
        a0 = wredsum(a0); a1 = wredsum(a1); a2 = wredsum(a2); a3 = wredsum(a3);
        float asel = (lane == 0) ? a0 : (lane == 1) ? a1 : (lane == 2) ? a2 : a3;
        if (half == 1 && lane < 4) spart[ui][lane] = asel;
        __syncthreads();
        if (half == 0) {
            float gv = 0.0f;
            if (lane < 4) {
                float x = asel + spart[ui][lane] + addv;
                gv = (lane == 2) ? tanhf(x) : 1.0f / (1.0f + expf(-x));
            }
            float i_ = __shfl_sync(0xffffffffu, gv, 0);
            float f_ = __shfl_sync(0xffffffffu, gv, 1);
            float gg = __shfl_sync(0xffffffffu, gv, 2);
            float o_ = __shfl_sync(0xffffffffu, gv, 3);
            if (lane == 0) {
                c = f_ * c + i_ * gg;
                float h = o_ * tanhf(c);
                g_h[cur ^ 1][unit] = h;
                if (WRITE_SEQ) seq[(size_t)t * HSZ + unit] = h;
                if (WRITE_LAST && t == TXN - 1) g_hlast[unit] = h;
            }
        }
        gbar(bar, epoch);
        cur ^= 1;
    }
}

// ---------------- fc + relu (fp64, off hot path) ----------------
__global__ void fc_relu(const float* __restrict__ W, const float* __restrict__ b,
                        const float* __restrict__ in, float* __restrict__ out) {
    __shared__ double red[8];
    int r = blockIdx.x, tid = threadIdx.x, wid = tid >> 5, lane = tid & 31;
    const float* wr = W + (size_t)r * 1024;
    float4 w = __ldg((const float4*)(wr + tid * 4));
    float4 v = __ldg((const float4*)(in + tid * 4));
    double acc = (double)(w.x * v.x) + (double)(w.y * v.y) +
                 (double)(w.z * v.z) + (double)(w.w * v.w);
    acc = wredsum_d(acc);
    if (lane == 0) red[wid] = acc;
    __syncthreads();
    if (tid == 0) {
        double s = 0;
#pragma unroll
        for (int i = 0; i < 8; i++) s += red[i];
        double val = s + (double)__ldg(b + r);
        out[r] = (float)(val > 0.0 ? val : 0.0);
    }
}

// ---------------- persistent greedy decoder (int8 dp4a projection + fp32 rescue) ----------------
#define DECT 512
__global__ void __launch_bounds__(DECT, 1)
decoder_kernel(
    const float* __restrict__ dWih0, const float* __restrict__ dWhh0, const float* __restrict__ db0,
    const float* __restrict__ dWih1, const float* __restrict__ dWhh1, const float* __restrict__ db1,
    const float* __restrict__ outw, const float* __restrict__ outb,
    const int* __restrict__ y, float* __restrict__ out) {
    __shared__ float sh0[HSZ];
    __shared__ float sh1[HSZ];
    __shared__ unsigned sh1q[HSZ / 4];            // int8-quantized h1
    __shared__ float c0s[HSZ];
    __shared__ float wih0s[G4];
    __shared__ float b0s[G4];
    __shared__ float slg[16][16];                 // per-warp logit stash
    __shared__ float redm[16];
    __shared__ float shsc;                        // h quant scale
    __shared__ unsigned long long skeys[16];
    int tid = threadIdx.x, wid = tid >> 5, lane = tid & 31;
    int unit = wid * gridDim.x + blockIdx.x;
    unsigned int epoch = 0;
    unsigned int* bar = &g_bars[2];

    for (int i = tid; i < G4; i += DECT) {
        wih0s[i] = __ldg(dWih0 + i);
        b0s[i] = __ldg(db0 + i);
    }
    for (int i = tid; i < HSZ; i += DECT) {
        float v = __ldg(&g_hinit[i]);
        c0s[i] = v;
        sh0[i] = v;
    }
    __syncthreads();

    float c1 = 0.0f;
    if (unit < HSZ) c1 = __ldg(&g_hinit[unit]);

    float ah1p0 = 0, ah1p1 = 0, ah1p2 = 0, ah1p3 = 0;
    if (unit < HSZ) {
        float w0 = 0, w1 = 0, w2 = 0, w3 = 0;
        const float* bh0 = dWhh0 + (size_t)unit * 1024;
        const float* bh1 = dWhh1 + (size_t)unit * 1024;
#pragma unroll
        for (int k = 0; k < 8; k++) {
            int j = (k * 32 + lane) << 2;
            float4 h4 = *(float4*)(sh0 + j);
            float4 w;
            w = __ldg((const float4*)(bh0 + j));
            w0 += w.x * h4.x + w.y * h4.y + w.z * h4.z + w.w * h4.w;
            w = __ldg((const float4*)(bh0 + (1 << 20) + j));
            w1 += w.x * h4.x + w.y * h4.y + w.z * h4.z + w.w * h4.w;
            w = __ldg((const float4*)(bh0 + (2 << 20) + j));
            w2 += w.x * h4.x + w.y * h4.y + w.z * h4.z + w.w * h4.w;
            w = __ldg((const float4*)(bh0 + (3 << 20) + j));
            w3 += w.x * h4.x + w.y * h4.y + w.z * h4.z + w.w * h4.w;
            w = __ldg((const float4*)(bh1 + j));
            ah1p0 += w.x * h4.x + w.y * h4.y + w.z * h4.z + w.w * h4.w;
            w = __ldg((const float4*)(bh1 + (1 << 20) + j));
            ah1p1 += w.x * h4.x + w.y * h4.y + w.z * h4.z + w.w * h4.w;
            w = __ldg((const float4*)(bh1 + (2 << 20) + j));
            ah1p2 += w.x * h4.x + w.y * h4.y + w.z * h4.z + w.w * h4.w;
            w = __ldg((const float4*)(bh1 + (3 << 20) + j));
            ah1p3 += w.x * h4.x + w.y * h4.y + w.z * h4.z + w.w * h4.w;
        }
        w0 = wredsum(w0); w1 = wredsum(w1); w2 = wredsum(w2); w3 = wredsum(w3);
        ah1p0 = wredsum(ah1p0); ah1p1 = wredsum(ah1p1);
        ah1p2 = wredsum(ah1p2); ah1p3 = wredsum(ah1p3);
        float wsel = (lane == 0) ? w0 : (lane == 1) ? w1 : (lane == 2) ? w2 : w3;
        if (lane < 4) g_aw0[0][lane * 1024 + unit] = wsel;
    }
    gbar(bar, epoch);

    float xt0 = (float)__ldg(&y[0]);
    int gw = blockIdx.x * 16 + wid, nw = gridDim.x * 16;

    for (int t = 0; t < TYN - 1; t++) {
        float xt;
        if (t == 0) xt = xt0;
        else {
            unsigned long long key = __ldcg(&g_amax[t - 1]);
            xt = (float)(0xFFFFFFFFu - (unsigned int)(key & 0xFFFFFFFFull));
        }
        // ---- phase A: replicated layer0 ----
        {
            const float* aw = &g_aw0[t & 1][0];
#pragma unroll
            for (int uu = 0; uu < 2; uu++) {
                int u = tid + uu * DECT;
                float x0 = __ldcg(aw + u)        + (wih0s[u] * xt        + b0s[u]);
                float x1 = __ldcg(aw + 1024 + u) + (wih0s[1024 + u] * xt + b0s[1024 + u]);
                float x2 = __ldcg(aw + 2048 + u) + (wih0s[2048 + u] * xt + b0s[2048 + u]);
                float x3 = __ldcg(aw + 3072 + u) + (wih0s[3072 + u] * xt + b0s[3072 + u]);
                float i_ = 1.0f / (1.0f + expf(-x0));
                float f_ = 1.0f / (1.0f + expf(-x1));
                float gg = tanhf(x2);
                float o_ = 1.0f / (1.0f + expf(-x3));
                float c = f_ * c0s[u] + i_ * gg;
                c0s[u] = c;
                sh0[u] = o_ * tanhf(c);
            }
        }
        __syncthreads();
        // ---- phase B ----
        if (unit < HSZ) {
            float ai0 = 0, ai1 = 0, ai2 = 0, ai3 = 0;
            float w0 = 0, w1 = 0, w2 = 0, w3 = 0;
            const float* bi = dWih1 + (size_t)unit * 1024;
            const float* bh0 = dWhh0 + (size_t)unit * 1024;
#pragma unroll
            for (int k = 0; k < 8; k++) {
                int j = (k * 32 + lane) << 2;
                float4 h4 = *(float4*)(sh0 + j);
                float4 w;
                w = __ldg((const float4*)(bi + j));
                ai0 += w.x * h4.x + w.y * h4.y + w.z * h4.z + w.w * h4.w;
                w = __ldg((const float4*)(bi + (1 << 20) + j));
                ai1 += w.x * h4.x + w.y * h4.y + w.z * h4.z + w.w * h4.w;
                w = __ldg((const float4*)(bi + (2 << 20) + j));
                ai2 += w.x * h4.x + w.y * h4.y + w.z * h4.z + w.w * h4.w;
                w = __ldg((const float4*)(bi + (3 << 20) + j));
                ai3 += w.x * h4.x + w.y * h4.y + w.z * h4.z + w.w * h4.w;
                w = __ldg((const float4*)(bh0 + j));
                w0 += w.x * h4.x + w.y * h4.y + w.z * h4.z + w.w * h4.w;
                w = __ldg((const float4*)(bh0 + (1 << 20) + j));
                w1 += w.x * h4.x + w.y * h4.y + w.z * h4.z + w.w * h4.w;
                w = __ldg((const float4*)(bh0 + (2 << 20) + j));
                w2 += w.x * h4.x + w.y * h4.y + w.z * h4.z + w.w * h4.w;
                w = __ldg((const float4*)(bh0 + (3 << 20) + j));
                w3 += w.x * h4.x + w.y * h4.y + w.z * h4.z + w.w * h4.w;
            }
            ai0 = wredsum(ai0); ai1 = wredsum(ai1); ai2 = wredsum(ai2); ai3 = wredsum(ai3);
            w0 = wredsum(w0); w1 = wredsum(w1); w2 = wredsum(w2); w3 = wredsum(w3);
            float wsel = (lane == 0) ? w0 : (lane == 1) ? w1 : (lane == 2) ? w2 : w3;
            if (lane < 4) g_aw0[(t + 1) & 1][lane * 1024 + unit] = wsel;
            float addv = 0.0f;
            if (lane < 4) {
                float ap = (lane == 0) ? ah1p0 : (lane == 1) ? ah1p1
                         : (lane == 2) ? ah1p2 : ah1p3;
                addv = ap + __ldg(db1 + unit + lane * 1024);
            }
            float i_, f_, gg, o_;
            gates4_f(ai0, ai1, ai2, ai3, addv, lane, i_, f_, gg, o_);
            if (lane == 0) {
                c1 = f_ * c1 + i_ * gg;
                g_d1f[unit] = o_ * tanhf(c1);
            }
        }
        gbar(bar, epoch);
        // ---- phase C: h1 load + quantize, Whh1 precompute, int8 projection, rescue ----
        if (tid < 256)
            *(float4*)(sh1 + tid * 4) = __ldcg((const float4*)(&g_d1f[tid * 4]));
        __syncthreads();
        // block max |h1|
        {
            float m = fmaxf(fabsf(sh1[tid * 2]), fabsf(sh1[tid * 2 + 1]));
            m = wredmax(m);
            if (lane == 0) redm[wid] = m;
        }
        __syncthreads();
        if (tid == 0) {
            float mm = redm[0];
#pragma unroll
            for (int i = 1; i < 16; i++) mm = fmaxf(mm, redm[i]);
            shsc = fmaxf(mm, 1e-20f) / 127.0f;
        }
        __syncthreads();
        {
            float hinv = 127.0f / (shsc * 127.0f);
            if (tid < 256)
                sh1q[tid] = pack4i8(sh1[4 * tid], sh1[4 * tid + 1],
                                    sh1[4 * tid + 2], sh1[4 * tid + 3], hinv);
        }
        if (unit < HSZ) {
            ah1p0 = 0; ah1p1 = 0; ah1p2 = 0; ah1p3 = 0;
            const float* bh1 = dWhh1 + (size_t)unit * 1024;
#pragma unroll
            for (int k = 0; k < 8; k++) {
                int j = (k * 32 + lane) << 2;
                float4 h4 = *(float4*)(sh1 + j);
                float4 w;
                w = __ldg((const float4*)(bh1 + j));
                ah1p0 += w.x * h4.x + w.y * h4.y + w.z * h4.z + w.w * h4.w;
                w = __ldg((const float4*)(bh1 + (1 << 20) + j));
                ah1p1 += w.x * h4.x + w.y * h4.y + w.z * h4.z + w.w * h4.w;
                w = __ldg((const float4*)(bh1 + (2 << 20) + j));
                ah1p2 += w.x * h4.x + w.y * h4.y + w.z * h4.z + w.w * h4.w;
                w = __ldg((const float4*)(bh1 + (3 << 20) + j));
                ah1p3 += w.x * h4.x + w.y * h4.y + w.z * h4.z + w.w * h4.w;
            }
            ah1p0 = wredsum(ah1p0); ah1p1 = wredsum(ah1p1);
            ah1p2 = wredsum(ah1p2); ah1p3 = wredsum(ah1p3);
        }
        __syncthreads();
        float hsc = shsc;
        float bestv = -INFINITY; int besti = 0;
        float* orow = out + (size_t)(t + 1) * VSZ;
        int r = gw;
        int nlg = 0;
        for (; r + nw < VSZ; r += 2 * nw) {
            int r2 = r + nw;
            const uint4* wr0 = (const uint4*)(g_owi8 + (size_t)r * 256);
            const uint4* wr1 = (const uint4*)(g_owi8 + (size_t)r2 * 256);
            int dA = 0, dB = 0;
#pragma unroll
            for (int k = 0; k < 2; k++) {
                int q = k * 32 + lane;
                uint4 wa = __ldcs(wr0 + q);
                uint4 wb = __ldcs(wr1 + q);
                int h0 = (int)sh1q[4 * q], h1 = (int)sh1q[4 * q + 1];
                int h2 = (int)sh1q[4 * q + 2], h3 = (int)sh1q[4 * q + 3];
                dA = __dp4a((int)wa.x, h0, dA); dA = __dp4a((int)wa.y, h1, dA);
                dA = __dp4a((int)wa.z, h2, dA); dA = __dp4a((int)wa.w, h3, dA);
                dB = __dp4a((int)wb.x, h0, dB); dB = __dp4a((int)wb.y, h1, dB);
                dB = __dp4a((int)wb.z, h2, dB); dB = __dp4a((int)wb.w, h3, dB);
            }
            dA = wredsum_i(dA);
            dB = wredsum_i(dB);
            if (lane == 0) {
                float lgA = (float)dA * (__ldg(g_wsc + r) * hsc) + __ldg(outb + r);
                float lgB = (float)dB * (__ldg(g_wsc + r2) * hsc) + __ldg(outb + r2);
                orow[r] = lgA;
                orow[r2] = lgB;
                slg[wid][nlg] = lgA;
                slg[wid][nlg + 1] = lgB;
                if (lgA > bestv) { bestv = lgA; besti = r; }
                if (lgB > bestv) { bestv = lgB; besti = r2; }
            }
            nlg += 2;
        }
        if (r < VSZ) {
            const uint4* wr0 = (const uint4*)(g_owi8 + (size_t)r * 256);
            int dA = 0;
#pragma unroll
            for (int k = 0; k < 2; k++) {
                int q = k * 32 + lane;
                uint4 wa = __ldcs(wr0 + q);
                dA = __dp4a((int)wa.x, (int)sh1q[4 * q], dA);
                dA = __dp4a((int)wa.y, (int)sh1q[4 * q + 1], dA);
                dA = __dp4a((int)wa.z, (int)sh1q[4 * q + 2], dA);
                dA = __dp4a((int)wa.w, (int)sh1q[4 * q + 3], dA);
            }
            dA = wredsum_i(dA);
            if (lane == 0) {
                float lg = (float)dA * (__ldg(g_wsc + r) * hsc) + __ldg(outb + r);
                orow[r] = lg;
                slg[wid][nlg] = lg;
                if (lg > bestv) { bestv = lg; besti = r; }
            }
        }
        __syncwarp();
        // ---- fp32 rescue vs warp-local best, logits replayed from SMEM stash ----
        {
            float thresh = __shfl_sync(0xffffffffu, bestv, 0) - MARGIN;
            unsigned long long bkey2 = 0ull;
            int rr = gw, k = 0;
            for (; rr < VSZ; rr += nw, k++) {
                float lv = slg[wid][k];
                if (lv >= thresh) {
                    const float* wrf = outw + (size_t)rr * 1024;
                    float p0 = 0, p1 = 0;
#pragma unroll
                    for (int kk = 0; kk < 8; kk += 2) {
                        int j0 = (kk * 32 + lane) << 2;
                        int j1 = ((kk + 1) * 32 + lane) << 2;
                        float4 wa0 = __ldg((const float4*)(wrf + j0));
                        float4 wa1 = __ldg((const float4*)(wrf + j1));
                        float4 h40 = *(float4*)(sh1 + j0);
                        float4 h41 = *(float4*)(sh1 + j1);
                        p0 += wa0.x * h40.x + wa0.y * h40.y + wa0.z * h40.z + wa0.w * h40.w;
                        p1 += wa1.x * h41.x + wa1.y * h41.y + wa1.z * h41.z + wa1.w * h41.w;
                    }
                    float accf = wredsum(p0 + p1);
                    if (lane == 0) {
                        float lgf = accf + __ldg(outb + rr);
                        orow[rr] = lgf;
                        unsigned long long kx = mkkey(lgf, rr);
                        if (kx > bkey2) bkey2 = kx;
                    }
                }
            }
            if (lane == 0) skeys[wid] = bkey2;
        }
        __syncthreads();
        if (tid == 0) {
            unsigned long long k0 = skeys[0];
#pragma unroll
            for (int w = 1; w < 16; w++) if (skeys[w] > k0) k0 = skeys[w];
            atomicMax(&g_amax[t], k0);
        }
        gbar(bar, epoch);
    }
}

// ---------------- final log_softmax over rows (in place) ----------------
__global__ void logsoftmax_kernel(float* __restrict__ out) {
    int row = blockIdx.x, tid = threadIdx.x, wid = tid >> 5, lane = tid & 31;
    float* p = out + (size_t)row * VSZ;
    if (row == 0) {
        float v = -(float)log((double)VSZ);
        for (int i = tid; i < VSZ; i += blockDim.x) p[i] = v;
        return;
    }
    __shared__ double redd[8];
    __shared__ float redf[8];
    __shared__ float bcf;
    __shared__ double bcd;
    float m = -INFINITY;
    for (int i = tid; i < VSZ; i += blockDim.x) m = fmaxf(m, p[i]);
#pragma unroll
    for (int o = 16; o; o >>= 1) m = fmaxf(m, __shfl_xor_sync(0xffffffffu, m, o));
    if (lane == 0) redf[wid] = m;
    __syncthreads();
    if (tid == 0) {
        float mm = redf[0];
#pragma unroll
        for (int i = 1; i < 8; i++) mm = fmaxf(mm, redf[i]);
        bcf = mm;
    }
    __syncthreads();
    m = bcf;
    double s = 0;
    for (int i = tid; i < VSZ; i += blockDim.x) s += (double)expf(p[i] - m);
    s = wredsum_d(s);
    if (lane == 0) redd[wid] = s;
    __syncthreads();
    if (tid == 0) {
        double ss = 0;
#pragma unroll
        for (int i = 0; i < 8; i++) ss += redd[i];
        bcd = (double)m + log(ss);
    }
    __syncthreads();
    double lse = bcd;
    for (int i = tid; i < VSZ; i += blockDim.x) p[i] = (float)((double)p[i] - lse);
}

// ---------------- launch ----------------
extern "C" void kernel_launch(void* const* d_in, const int* in_sizes, int n_in,
                              void* d_out, int out_size) {
    const int*   x     = (const int*)d_in[0];
    const int*   y     = (const int*)d_in[1];
    const float* emb   = (const float*)d_in[2];
    const float* eWih0 = (const float*)d_in[3];
    const float* eWhh0 = (const float*)d_in[4];
    const float* eb0   = (const float*)d_in[5];
    const float* eWih1 = (const float*)d_in[6];
    const float* eWhh1 = (const float*)d_in[7];
    const float* eb1   = (const float*)d_in[8];
    const float* fc1w  = (const float*)d_in[9];
    const float* fc1b  = (const float*)d_in[10];
    const float* fc2w  = (const float*)d_in[11];
    const float* fc2b  = (const float*)d_in[12];
    const float* dWih0 = (const float*)d_in[13];
    const float* dWhh0 = (const float*)d_in[14];
    const float* db0   = (const float*)d_in[15];
    const float* dWih1 = (const float*)d_in[16];
    const float* dWhh1 = (const float*)d_in[17];
    const float* db1   = (const float*)d_in[18];
    const float* outw  = (const float*)d_in[19];
    const float* outb  = (const float*)d_in[20];
    float* out = (float*)d_out;

    float *pG = nullptr, *pSeq = nullptr, *pF1 = nullptr, *pHinit = nullptr, *pHlast = nullptr;
    cudaGetSymbolAddress((void**)&pG, g_G);
    cudaGetSymbolAddress((void**)&pSeq, g_seq);
    cudaGetSymbolAddress((void**)&pF1, g_f1);
    cudaGetSymbolAddress((void**)&pHinit, g_hinit);
    cudaGetSymbolAddress((void**)&pHlast, g_hlast);

    int dev = 0, nsm = 148;
    cudaGetDevice(&dev);
    cudaDeviceGetAttribute(&nsm, cudaDevAttrMultiProcessorCount, dev);
    if (nsm < 128) nsm = 128;

    init_kernel<<<1, 512>>>();
    conv_i8<<<VSZ, 128>>>(outw);
    gemm_nt<ESZ><<<dim3(64, 32), 256>>>(emb, x, eWih0, eb0, pG);
    enc_scan<1, 0, 0><<<128, 512>>>(eWhh0, pG, pSeq);
    gemm_nt<HSZ><<<dim3(64, 32), 256>>>(pSeq, nullptr, eWih1, eb1, pG);
    enc_scan<0, 1, 1><<<128, 512>>>(eWhh1, pG, nullptr);
    fc_relu<<<1024, 256>>>(fc1w, fc1b, pHlast, pF1);
    fc_relu<<<1024, 256>>>(fc2w, fc2b, pF1, pHinit);
    decoder_kernel<<<nsm, DECT>>>(dWih0, dWhh0, db0, dWih1, dWhh1, db1, outw, outb, y, out);
    logsoftmax_kernel<<<TYN, 256>>>(out);
}